// round 6
// baseline (speedup 1.0000x reference)
#include <cuda_runtime.h>
#include <cstdint>

// ---- problem constants ----
#define BATCH   1024
#define NNODES  100
#define KD      640      // key dim (5*128)
#define KD4     160      // key dim in float4
#define POOL    128
#define TOPK    4
#define PD      2304     // prompt dim
#define PD4     576

// ---- output layout (flat float32, reference return order) ----
#define OUT_RS  (BATCH*TOPK*PD)          // 9437184
#define OUT_SIM (OUT_RS + 1)             // 9437185
#define OUT_US  (OUT_SIM + BATCH*POOL)   // 9568257

// ---- role partition by blockIdx.x (dependencies point to LOWER bids ->
//      with in-order CTA dispatch this is deadlock-free) ----
#define B_KEY0   0        // 128 key-normalize blocks (done first!)
#define B_X0     128      // 1024 x-row mean+normalize blocks
#define B_KB0    1152     // 256 sim/top-k blocks (4 rows each)
#define B_KC0    1408     // 1024 gather blocks
#define B_FIN    2432     // 1 final block
#define NBLOCKS  2433

// ---- device scratch (zero-initialized at module load; final block
//      resets all flags each run so graph replays start clean) ----
__device__ float g_xnorm[BATCH * KD];
__device__ float g_keynorm[POOL * KD];
__device__ int   g_idx[BATCH * TOPK];
__device__ float g_partial[256];
__device__ int   g_grp[256];     // per-4-row-group x-done count (==4)
__device__ int   g_keys;         // key blocks done (==128)
__device__ int   g_kbflag[256];  // sim block done
__device__ int   g_kbcnt;        // sim blocks done (==256)
__device__ int   g_kccnt;        // gather blocks done (==1024)

// ---- f32x2 packed-FMA helpers (sm_103a) ----
__device__ __forceinline__ void fma2(unsigned long long& acc,
                                     unsigned long long a,
                                     unsigned long long b) {
    asm("fma.rn.f32x2 %0, %1, %2, %0;" : "+l"(acc) : "l"(a), "l"(b));
}
__device__ __forceinline__ float unpack_sum(unsigned long long v) {
    float lo, hi;
    asm("mov.b64 {%0, %1}, %2;" : "=f"(lo), "=f"(hi) : "l"(v));
    return lo + hi;
}
__device__ __forceinline__ void waitge(volatile int* p, int tgt) {
    while (*p < tgt) __nanosleep(128);
}

// ============================================================
__global__ __launch_bounds__(512, 2)
void mega(const float4* __restrict__ x, const float4* __restrict__ pk,
          const float4* __restrict__ prompt, float* __restrict__ out) {
    __shared__ float4 part[2][160];
    __shared__ float  wss[8];
    __shared__ float  xs[4][644];
    __shared__ float  sims[4][132];
    __shared__ float  wsum[4];
    __shared__ float  red[256];
    __shared__ int    histo[128];

    const int bid  = blockIdx.x;
    const int t    = threadIdx.x;
    const int w    = t >> 5, lane = t & 31;

    if (bid < B_X0) {
        // ---------------- key normalize (p = bid) ----------------
        const int p = bid;
        float4 v = make_float4(0.f, 0.f, 0.f, 0.f);
        float ss = 0.f;
        if (t < 160) {
            v = pk[(size_t)p * KD4 + t];
            ss = v.x*v.x + v.y*v.y + v.z*v.z + v.w*v.w;
        }
        #pragma unroll
        for (int o = 16; o; o >>= 1) ss += __shfl_xor_sync(0xffffffffu, ss, o);
        if (lane == 0 && w < 5) wss[w] = ss;
        __syncthreads();
        if (t < 160) {
            float tot = wss[0] + wss[1] + wss[2] + wss[3] + wss[4];
            tot = fmaxf(tot, 1e-12f);
            float rs = rsqrtf(tot);
            rs = rs * (1.5f - 0.5f * tot * rs * rs);   // NR refine
            float4* o4 = reinterpret_cast<float4*>(g_keynorm);
            o4[(size_t)p * KD4 + t] = make_float4(v.x*rs, v.y*rs, v.z*rs, v.w*rs);
        }
        __syncthreads();
        if (t == 0) { __threadfence(); atomicAdd(&g_keys, 1); }

    } else if (bid < B_KB0) {
        // ---------------- x-row mean + L2 normalize ----------------
        // Normalizing the SUM == normalizing the mean (scale invariance).
        const int row = bid - B_X0;
        const int c = t % 160, y = t / 160;             // y 0..3 (y==3 idle)
        const int lo = (y == 0) ? 0 : 34 + 33 * (y - 1);
        const int nn = (y == 0) ? 34 : 33;
        float4 a = make_float4(0.f, 0.f, 0.f, 0.f);
        if (y < 3) {
            const float4* xp = x + (size_t)row * (NNODES * KD4)
                                 + (size_t)lo * KD4 + c;
            #pragma unroll 8
            for (int n = 0; n < nn; n++) {
                float4 v = xp[(size_t)n * KD4];
                a.x += v.x; a.y += v.y; a.z += v.z; a.w += v.w;
            }
        }
        if (y == 1) part[0][c] = a;
        if (y == 2) part[1][c] = a;
        __syncthreads();
        float ss = 0.f;
        if (y == 0) {
            float4 b0 = part[0][c], b1 = part[1][c];
            a.x += b0.x + b1.x; a.y += b0.y + b1.y;
            a.z += b0.z + b1.z; a.w += b0.w + b1.w;
            ss = a.x*a.x + a.y*a.y + a.z*a.z + a.w*a.w;
        }
        #pragma unroll
        for (int o = 16; o; o >>= 1) ss += __shfl_xor_sync(0xffffffffu, ss, o);
        if (lane == 0 && w < 5) wss[w] = ss;
        __syncthreads();
        if (y == 0) {
            float tot = wss[0] + wss[1] + wss[2] + wss[3] + wss[4];
            tot = fmaxf(tot, 1e-12f);
            float rs = rsqrtf(tot);
            rs = rs * (1.5f - 0.5f * tot * rs * rs);
            float4* o4 = reinterpret_cast<float4*>(g_xnorm);
            o4[(size_t)row * KD4 + c] = make_float4(a.x*rs, a.y*rs, a.z*rs, a.w*rs);
        }
        __syncthreads();
        if (t == 0) { __threadfence(); atomicAdd(&g_grp[row >> 2], 1); }

    } else if (bid < B_KC0) {
        // ---------------- sim GEMM (4 rows x 128 pools) + top-4 ----------------
        const int i  = bid - B_KB0;
        const int rb = i * 4;
        if (t == 0) {
            waitge(&g_keys, POOL);
            waitge(&g_grp[i], 4);
            __threadfence();
        }
        __syncthreads();

        // stage 4 x rows (640 float4)
        {
            const float4* xg = reinterpret_cast<const float4*>(g_xnorm);
            int l = t;                                   // 0..511
            {
                int r = l / 160, col = l - r * 160;
                *reinterpret_cast<float4*>(&xs[r][col * 4]) =
                    xg[(size_t)(rb + r) * KD4 + col];
            }
            l = t + 512;
            if (l < 640) {
                int r = l / 160, col = l - r * 160;
                *reinterpret_cast<float4*>(&xs[r][col * 4]) =
                    xg[(size_t)(rb + r) * KD4 + col];
            }
        }
        __syncthreads();

        const int pg = t >> 4;             // 0..31 -> pools pg*4..+3
        const int ds = t & 15;             // dim slot
        const ulonglong2* kg = reinterpret_cast<const ulonglong2*>(g_keynorm);

        unsigned long long acc[4][4];      // [pool u][row r]
        #pragma unroll
        for (int u = 0; u < 4; u++)
            #pragma unroll
            for (int r = 0; r < 4; r++) acc[u][r] = 0ull;

        #pragma unroll
        for (int c = 0; c < 10; c++) {
            ulonglong2 kv[4];
            #pragma unroll
            for (int u = 0; u < 4; u++)
                kv[u] = kg[(size_t)(pg * 4 + u) * KD4 + c * 16 + ds];
            #pragma unroll
            for (int r = 0; r < 4; r++) {
                ulonglong2 xv = *reinterpret_cast<const ulonglong2*>(
                    &xs[r][c * 64 + ds * 4]);
                #pragma unroll
                for (int u = 0; u < 4; u++) {
                    fma2(acc[u][r], xv.x, kv[u].x);
                    fma2(acc[u][r], xv.y, kv[u].y);
                }
            }
        }
        #pragma unroll
        for (int u = 0; u < 4; u++) {
            #pragma unroll
            for (int r = 0; r < 4; r++) {
                float v = unpack_sum(acc[u][r]);
                #pragma unroll
                for (int o = 8; o; o >>= 1) v += __shfl_xor_sync(0xffffffffu, v, o);
                if (ds == 0) sims[r][pg * 4 + u] = v;
            }
        }
        __syncthreads();

        // similarity out: 4x128 = 512, one per thread
        {
            int rr = t >> 7, pp = t & 127;
            out[OUT_SIM + (size_t)(rb + rr) * POOL + pp] = sims[rr][pp];
        }

        // top-4: warps 0..3 -> rows 0..3 (monotone-bits composite key,
        // smallest index on ties -> matches jax.lax.top_k)
        if (w < 4) {
            float vals[4];
            #pragma unroll
            for (int s = 0; s < 4; s++) vals[s] = sims[w][lane + 32*s];
            float vsum = 0.f;
            #pragma unroll
            for (int k = 0; k < TOPK; k++) {
                unsigned long long best = 0ull;
                #pragma unroll
                for (int s = 0; s < 4; s++) {
                    unsigned u = __float_as_uint(vals[s]);
                    u = (u & 0x80000000u) ? ~u : (u | 0x80000000u);
                    unsigned long long comp =
                        ((unsigned long long)u << 32) | (127u - (lane + 32u*s));
                    if (comp > best) best = comp;
                }
                #pragma unroll
                for (int o = 16; o; o >>= 1) {
                    unsigned long long other = __shfl_xor_sync(0xffffffffu, best, o);
                    if (other > best) best = other;
                }
                unsigned pool = 127u - (unsigned)(best & 0xffffffffu);
                unsigned ub = (unsigned)(best >> 32);
                unsigned orig = (ub & 0x80000000u) ? (ub ^ 0x80000000u) : ~ub;
                vsum += __uint_as_float(orig);
                if (lane == (int)(pool & 31u)) vals[pool >> 5] = -1e30f;
                if (lane == 0) g_idx[(rb + w) * TOPK + k] = (int)pool;
            }
            if (lane == 0) wsum[w] = vsum;
        }
        __syncthreads();
        if (t == 0) {
            g_partial[i] = wsum[0] + wsum[1] + wsum[2] + wsum[3];  // fixed order
            __threadfence();
            atomicAdd(&g_kbflag[i], 1);
            atomicAdd(&g_kbcnt, 1);
        }

    } else if (bid < B_FIN) {
        // ---------------- gather selected prompts ----------------
        const int b = bid - B_KC0;
        if (t == 0) { waitge(&g_kbflag[b >> 2], 1); __threadfence(); }
        __syncthreads();

        int idxs[TOPK];
        #pragma unroll
        for (int k = 0; k < TOPK; k++) idxs[k] = g_idx[b * TOPK + k];

        float4 vals[4];
        #pragma unroll
        for (int j = 0; j < 4; j++) {
            int pos = t + 512 * j;          // 0..2047
            int k   = pos / PD4;
            int off = pos - k * PD4;
            vals[j] = prompt[(size_t)idxs[k] * PD4 + off];
        }
        float4 vtail = make_float4(0.f,0.f,0.f,0.f);
        if (t < 256) vtail = prompt[(size_t)idxs[3] * PD4 + (2048 + t - 3 * PD4)];

        float4* dst = reinterpret_cast<float4*>(out) + (size_t)b * (TOPK * PD4);
        #pragma unroll
        for (int j = 0; j < 4; j++) dst[t + 512 * j] = vals[j];
        if (t < 256) dst[2048 + t] = vtail;

        __syncthreads();
        if (t == 0) atomicAdd(&g_kccnt, 1);   // past our wait -> reset is safe

    } else {
        // ---------------- final: reduce_sim + usage + flag reset ----------------
        if (t == 0) { waitge(&g_kbcnt, 256); __threadfence(); }
        __syncthreads();
        if (t < 256) red[t] = g_partial[t];
        if (t < 128) histo[t] = 0;
        __syncthreads();
        #pragma unroll
        for (int o = 128; o; o >>= 1) {
            if (t < o && t + o < 256) red[t] += red[t + o];
            __syncthreads();
        }
        if (t == 0) out[OUT_RS] = red[0] * (1.0f / (float)BATCH);
        #pragma unroll
        for (int j = 0; j < 8; j++)
            atomicAdd(&histo[g_idx[t * 8 + j]], 1);
        __syncthreads();
        if (t < 128) out[OUT_US + t] = (float)histo[t];

        // wait until every gather block has passed its flag-wait, then reset
        if (t == 0) waitge(&g_kccnt, 1024);
        __syncthreads();
        if (t < 256) { g_grp[t] = 0; g_kbflag[t] = 0; }
        if (t == 256) g_keys = 0;
        if (t == 257) g_kbcnt = 0;
        if (t == 258) g_kccnt = 0;
    }
}

// ============================================================
extern "C" void kernel_launch(void* const* d_in, const int* in_sizes, int n_in,
                              void* d_out, int out_size) {
    const float* x      = (const float*)d_in[0];  // [1024, 100, 640]
    const float* prompt = (const float*)d_in[1];  // [128, 1, 2304]
    const float* pkey   = (const float*)d_in[2];  // [128, 640]
    float* out = (float*)d_out;

    mega<<<NBLOCKS, 512>>>(reinterpret_cast<const float4*>(x),
                           reinterpret_cast<const float4*>(pkey),
                           reinterpret_cast<const float4*>(prompt), out);
}

// round 7
// speedup vs baseline: 1.0300x; 1.0300x over previous
#include <cuda_runtime.h>
#include <cstdint>

// ---- problem constants ----
#define BATCH   1024
#define NNODES  100
#define KD      640      // key dim (5*128)
#define KD4     160      // key dim in float4
#define POOL    128
#define TOPK    4
#define PD      2304     // prompt dim
#define PD4     576

// ---- output layout (flat float32, reference return order) ----
#define OUT_RS  (BATCH*TOPK*PD)          // 9437184
#define OUT_SIM (OUT_RS + 1)             // 9437185
#define OUT_US  (OUT_SIM + BATCH*POOL)   // 9568257

// ---- roles: bids 0..127 keys, 128..383 work (4 rows each), 384 final.
//      Only cross-block dep: work waits on keys (lower bids, wave-1). ----
#define B_WORK0  128
#define B_FIN    384
#define NBLOCKS  385

// ---- device scratch ----
__device__ float g_keynorm[POOL * KD];
__device__ int   g_idx[BATCH * TOPK];
__device__ float g_partial[256];
__device__ int   g_keys;    // key blocks done (==128)
__device__ int   g_done;    // work blocks done (==256)

// ---- f32x2 packed-FMA helpers (sm_103a) ----
__device__ __forceinline__ void fma2(unsigned long long& acc,
                                     unsigned long long a,
                                     unsigned long long b) {
    asm("fma.rn.f32x2 %0, %1, %2, %0;" : "+l"(acc) : "l"(a), "l"(b));
}
__device__ __forceinline__ float unpack_sum(unsigned long long v) {
    float lo, hi;
    asm("mov.b64 {%0, %1}, %2;" : "=f"(lo), "=f"(hi) : "l"(v));
    return lo + hi;
}
__device__ __forceinline__ void waitge(volatile int* p, int tgt) {
    while (*p < tgt) __nanosleep(64);
}

// ============================================================
__global__ __launch_bounds__(512, 2)
void mega(const float4* __restrict__ x, const float4* __restrict__ pk,
          const float4* __restrict__ prompt, float* __restrict__ out) {
    __shared__ float  xs[4][644];      // normalized rows (padded)
    __shared__ float4 part[2][160];
    __shared__ float  wss[8];
    __shared__ float  sims[4][132];
    __shared__ float  wsum[4];
    __shared__ int    sidx[16];

    const int bid  = blockIdx.x;
    const int t    = threadIdx.x;
    const int w    = t >> 5, lane = t & 31;

    if (bid < B_WORK0) {
        // ================= key normalize (p = bid) =================
        const int p = bid;
        float4 v = make_float4(0.f, 0.f, 0.f, 0.f);
        float ss = 0.f;
        if (t < 160) {
            v = pk[(size_t)p * KD4 + t];
            ss = v.x*v.x + v.y*v.y + v.z*v.z + v.w*v.w;
        }
        #pragma unroll
        for (int o = 16; o; o >>= 1) ss += __shfl_xor_sync(0xffffffffu, ss, o);
        if (lane == 0 && w < 5) wss[w] = ss;
        __syncthreads();
        if (t < 160) {
            float tot = wss[0] + wss[1] + wss[2] + wss[3] + wss[4];
            tot = fmaxf(tot, 1e-12f);
            float rs = rsqrtf(tot);
            rs = rs * (1.5f - 0.5f * tot * rs * rs);   // NR refine
            float4* o4 = reinterpret_cast<float4*>(g_keynorm);
            o4[(size_t)p * KD4 + t] = make_float4(v.x*rs, v.y*rs, v.z*rs, v.w*rs);
        }
        __syncthreads();
        if (t == 0) { __threadfence(); atomicAdd(&g_keys, 1); }

    } else if (bid < B_FIN) {
        // ================= self-sufficient work block =================
        const int i  = bid - B_WORK0;
        const int rb = i * 4;

        // ---- phase 1: mean + L2 normalize 4 rows -> smem (no global) ----
        // Normalizing the SUM == normalizing the mean (scale invariance).
        const int c = t % 160, y = t / 160;            // y 0..3 (y==3 idle)
        const int lo = (y == 0) ? 0 : 34 + 33 * (y - 1);
        const int nn = (y == 0) ? 34 : 33;
        #pragma unroll 1
        for (int r = 0; r < 4; r++) {
            float4 a = make_float4(0.f, 0.f, 0.f, 0.f);
            if (y < 3) {
                const float4* xp = x + (size_t)(rb + r) * (NNODES * KD4)
                                     + (size_t)lo * KD4 + c;
                #pragma unroll 11
                for (int n = 0; n < nn; n++) {
                    float4 v = xp[(size_t)n * KD4];
                    a.x += v.x; a.y += v.y; a.z += v.z; a.w += v.w;
                }
            }
            if (y == 1) part[0][c] = a;
            if (y == 2) part[1][c] = a;
            __syncthreads();
            float ss = 0.f;
            if (y == 0) {
                float4 b0 = part[0][c], b1 = part[1][c];
                a.x += b0.x + b1.x; a.y += b0.y + b1.y;
                a.z += b0.z + b1.z; a.w += b0.w + b1.w;
                ss = a.x*a.x + a.y*a.y + a.z*a.z + a.w*a.w;
            }
            #pragma unroll
            for (int o = 16; o; o >>= 1) ss += __shfl_xor_sync(0xffffffffu, ss, o);
            if (lane == 0 && w < 5) wss[w] = ss;
            __syncthreads();
            if (y == 0) {
                float tot = wss[0] + wss[1] + wss[2] + wss[3] + wss[4];
                tot = fmaxf(tot, 1e-12f);
                float rs = rsqrtf(tot);
                rs = rs * (1.5f - 0.5f * tot * rs * rs);
                xs[r][c*4+0] = a.x*rs; xs[r][c*4+1] = a.y*rs;
                xs[r][c*4+2] = a.z*rs; xs[r][c*4+3] = a.w*rs;
            }
            __syncthreads();
        }

        // ---- phase 2: wait keys (wave-1 blocks; effectively free) ----
        if (t == 0) { waitge(&g_keys, POOL); __threadfence(); }
        __syncthreads();

        // ---- phase 3: GEMM 4 rows x 128 pools (keys via L2 LDG) ----
        const int pg = t >> 4;             // 0..31 -> pools pg*4..+3
        const int ds = t & 15;             // dim slot
        const ulonglong2* kg = reinterpret_cast<const ulonglong2*>(g_keynorm);

        unsigned long long acc[4][4];      // [pool u][row r]
        #pragma unroll
        for (int u = 0; u < 4; u++)
            #pragma unroll
            for (int r = 0; r < 4; r++) acc[u][r] = 0ull;

        #pragma unroll
        for (int cc = 0; cc < 10; cc++) {
            ulonglong2 kv[4];
            #pragma unroll
            for (int u = 0; u < 4; u++)
                kv[u] = kg[(size_t)(pg * 4 + u) * KD4 + cc * 16 + ds];
            #pragma unroll
            for (int r = 0; r < 4; r++) {
                ulonglong2 xv = *reinterpret_cast<const ulonglong2*>(
                    &xs[r][cc * 64 + ds * 4]);
                #pragma unroll
                for (int u = 0; u < 4; u++) {
                    fma2(acc[u][r], xv.x, kv[u].x);
                    fma2(acc[u][r], xv.y, kv[u].y);
                }
            }
        }
        #pragma unroll
        for (int u = 0; u < 4; u++) {
            #pragma unroll
            for (int r = 0; r < 4; r++) {
                float v = unpack_sum(acc[u][r]);
                #pragma unroll
                for (int o = 8; o; o >>= 1) v += __shfl_xor_sync(0xffffffffu, v, o);
                if (ds == 0) sims[r][pg * 4 + u] = v;
            }
        }
        __syncthreads();

        // ---- sim out: 4x128, one elem per thread ----
        {
            int rr = t >> 7, pp = t & 127;
            out[OUT_SIM + (size_t)(rb + rr) * POOL + pp] = sims[rr][pp];
        }

        // ---- phase 4: top-4 (warps 0..3 -> rows 0..3) ----
        // monotone-bits composite key, smallest index on ties (jax.lax.top_k)
        if (w < 4) {
            float vals[4];
            #pragma unroll
            for (int s = 0; s < 4; s++) vals[s] = sims[w][lane + 32*s];
            float vsum = 0.f;
            #pragma unroll
            for (int k = 0; k < TOPK; k++) {
                unsigned long long best = 0ull;
                #pragma unroll
                for (int s = 0; s < 4; s++) {
                    unsigned u = __float_as_uint(vals[s]);
                    u = (u & 0x80000000u) ? ~u : (u | 0x80000000u);
                    unsigned long long comp =
                        ((unsigned long long)u << 32) | (127u - (lane + 32u*s));
                    if (comp > best) best = comp;
                }
                #pragma unroll
                for (int o = 16; o; o >>= 1) {
                    unsigned long long other = __shfl_xor_sync(0xffffffffu, best, o);
                    if (other > best) best = other;
                }
                unsigned pool = 127u - (unsigned)(best & 0xffffffffu);
                unsigned ub = (unsigned)(best >> 32);
                unsigned orig = (ub & 0x80000000u) ? (ub ^ 0x80000000u) : ~ub;
                vsum += __uint_as_float(orig);
                if (lane == (int)(pool & 31u)) vals[pool >> 5] = -1e30f;
                if (lane == 0) {
                    g_idx[(rb + w) * TOPK + k] = (int)pool;
                    sidx[w * 4 + k] = (int)pool;
                }
            }
            if (lane == 0) wsum[w] = vsum;
        }
        __syncthreads();

        // ---- phase 5: in-block gather: 16 segments x 576 f4 ----
        float4* outbp = reinterpret_cast<float4*>(out);
        #pragma unroll
        for (int s0 = 0; s0 < 18; s0 += 6) {
            float4 v[6]; int di[6];
            #pragma unroll
            for (int k = 0; k < 6; k++) {
                int idx = t + 512 * (s0 + k);     // 0..9215
                int seg = idx / PD4;
                int off = idx - seg * PD4;
                v[k]  = prompt[(size_t)sidx[seg] * PD4 + off];
                di[k] = (rb * 4 + seg) * PD4 + off;
            }
            #pragma unroll
            for (int k = 0; k < 6; k++) outbp[di[k]] = v[k];
        }

        if (t == 0) {
            g_partial[i] = wsum[0] + wsum[1] + wsum[2] + wsum[3]; // fixed order
            __threadfence();
            atomicAdd(&g_done, 1);
        }

    } else {
        // ================= final: reduce_sim + usage + reset =================
        __shared__ float red[256];
        __shared__ int   histo[128];
        if (t == 0) { waitge(&g_done, 256); __threadfence(); }
        __syncthreads();
        if (t < 256) red[t] = g_partial[t];
        if (t < 128) histo[t] = 0;
        __syncthreads();
        #pragma unroll
        for (int o = 128; o; o >>= 1) {
            if (t < o && t + o < 256) red[t] += red[t + o];
            __syncthreads();
        }
        if (t == 0) out[OUT_RS] = red[0] * (1.0f / (float)BATCH);
        #pragma unroll
        for (int j = 0; j < 8; j++)
            atomicAdd(&histo[g_idx[t * 8 + j]], 1);
        __syncthreads();
        if (t < 128) out[OUT_US + t] = (float)histo[t];
        // reset flags for next graph replay (all waiters already passed:
        // g_done==256 implies every work block finished, incl. key waits)
        if (t == 0) { g_keys = 0; g_done = 0; }
    }
}

// ============================================================
extern "C" void kernel_launch(void* const* d_in, const int* in_sizes, int n_in,
                              void* d_out, int out_size) {
    const float* x      = (const float*)d_in[0];  // [1024, 100, 640]
    const float* prompt = (const float*)d_in[1];  // [128, 1, 2304]
    const float* pkey   = (const float*)d_in[2];  // [128, 640]
    float* out = (float*)d_out;

    mega<<<NBLOCKS, 512>>>(reinterpret_cast<const float4*>(x),
                           reinterpret_cast<const float4*>(pkey),
                           reinterpret_cast<const float4*>(prompt), out);
}